// round 16
// baseline (speedup 1.0000x reference)
#include <cuda_runtime.h>
#include <math.h>
#include <float.h>

#define BB 8
#define NN 1024
#define KNN 20

// ---------------- static device scratch ----------------
__device__ float    g_G[(size_t)BB*NN*NN];        // pairwise 2*dot - sq[m]
__device__ float    g_SQ[BB*NN];
__device__ float    g_Z2[(size_t)BB*NN*512];      // [bn][2O]: Zn | Zc
__device__ float    g_FEAT[(size_t)BB*NN*512];    // concat features (bn, c)
__device__ float    g_YMAX[(size_t)BB*NN*256];
__device__ float    g_YMIN[(size_t)BB*NN*256];
__device__ double   g_SUM[512];
__device__ double   g_SUMSQ[512];
__device__ float    g_A[512];
__device__ float    g_Cc[512];
__device__ float    g_WCAT[90496];                // [Wn ; Wc-Wn] per block
__device__ unsigned g_MXU[BB*512];
__device__ unsigned g_MNU[BB*512];

__device__ __forceinline__ unsigned encf(float f) {
    unsigned b = __float_as_uint(f);
    return (b & 0x80000000u) ? ~b : (b | 0x80000000u);
}
__device__ __forceinline__ float decf(unsigned u) {
    return __uint_as_float((u & 0x80000000u) ? (u & 0x7FFFFFFFu) : ~u);
}

// ---- packed f32x2 helpers ----
__device__ __forceinline__ unsigned long long pk2(float v) {
    unsigned long long r;
    asm("mov.b64 %0, {%1,%1};" : "=l"(r) : "f"(v));
    return r;
}
__device__ __forceinline__ void ffma2(unsigned long long &d,
                                      unsigned long long a, unsigned long long b) {
    asm("fma.rn.f32x2 %0, %1, %2, %0;" : "+l"(d) : "l"(a), "l"(b));
}
__device__ __forceinline__ void unpk(unsigned long long v, float &lo, float &hi) {
    asm("mov.b64 {%0,%1}, %2;" : "=f"(lo), "=f"(hi) : "l"(v));
}

#define BPK_WORDS (16*132)          // u64 words per B buffer
#define BPK_BYTES (2*BPK_WORDS*8)   // dynamic smem bytes (both buffers)

// WCAT offsets: b1:0 (128x3), b2:384 (128x64), b3:8576 (256x64), b4:24960 (512x128)
__global__ void prep_kernel(const float* __restrict__ w1, const float* __restrict__ w2,
                            const float* __restrict__ w3, const float* __restrict__ w4) {
    int t = blockIdx.x * blockDim.x + threadIdx.x;
    if (t < 384) {
        int r = t/3, c = t%3;
        g_WCAT[t] = (r < 64) ? w1[r*6 + c] : (w1[(r-64)*6 + 3 + c] - w1[(r-64)*6 + c]);
        return;
    }
    int u = t - 384;
    if (u < 8192) {
        int r = u/64, c = u%64;
        g_WCAT[384 + u] = (r < 64) ? w2[r*128 + c] : (w2[(r-64)*128 + 64 + c] - w2[(r-64)*128 + c]);
        return;
    }
    u -= 8192;
    if (u < 16384) {
        int r = u/64, c = u%64;
        g_WCAT[8576 + u] = (r < 128) ? w3[r*128 + c] : (w3[(r-128)*128 + 64 + c] - w3[(r-128)*128 + c]);
        return;
    }
    u -= 16384;
    if (u < 65536) {
        int r = u/128, c = u%128;
        g_WCAT[24960 + u] = (r < 256) ? w4[r*256 + c] : (w4[(r-256)*256 + 128 + c] - w4[(r-256)*256 + c]);
        return;
    }
}

// ---- packed inner product over one 16-k tile: A float pairs, B pre-packed u64 ----
__device__ __forceinline__ void mm16_pk(unsigned long long acc2[4][8],
                                        const float (*sAk)[132],
                                        const unsigned long long* sBk,   // [16][132]
                                        int ty, int tx) {
    #pragma unroll
    for (int k = 0; k < 16; k++) {
        const ulonglong2* pa = (const ulonglong2*)&sAk[k][ty*8];
        ulonglong2 A01 = pa[0], A23 = pa[1];
        unsigned long long a2[4] = {A01.x, A01.y, A23.x, A23.y};
        const ulonglong2* pb = (const ulonglong2*)&sBk[k*132 + tx*8];
        ulonglong2 B01 = pb[0], B23 = pb[1], B45 = pb[2], B67 = pb[3];
        unsigned long long bb[8] = {B01.x, B01.y, B23.x, B23.y,
                                    B45.x, B45.y, B67.x, B67.y};
        #pragma unroll
        for (int i2 = 0; i2 < 4; i2++)
            #pragma unroll
            for (int j = 0; j < 8; j++)
                ffma2(acc2[i2][j], a2[i2], bb[j]);
    }
}

// =======================================================================
// Symmetric gram, double-buffered, f32x2 core with packed-B smem.
// =======================================================================
__global__ void __launch_bounds__(256, 2)
gram_sym(const float* __restrict__ A, int lda, int K) {
    __shared__ __align__(16) float sA[2][16][132];
    extern __shared__ __align__(16) unsigned long long sBp[];   // [2][16][132]

    int t  = threadIdx.x;
    int tx = t & 15, ty = t >> 4;
    int bz = blockIdx.z;

    int idx = blockIdx.x;
    int ib = 0;
    while (idx >= 8 - ib) { idx -= 8 - ib; ib++; }
    int jb = ib + idx;

    int arow0 = ib * 128;
    int brow0 = jb * 128;
    const float* Abase = A + (size_t)(bz*1024 + arow0) * lda;
    const float* Bbase = A + (size_t)(bz*1024 + brow0) * lda;

    unsigned long long acc2[4][8];
    #pragma unroll
    for (int i = 0; i < 4; i++)
        #pragma unroll
        for (int j = 0; j < 8; j++) acc2[i][j] = 0ull;

    int lrow[2], lq[2];
    #pragma unroll
    for (int rr = 0; rr < 2; rr++) { int f = t + rr*256; lrow[rr] = f >> 2; lq[rr] = f & 3; }

    float4 va[2], vb[2];
    #pragma unroll
    for (int rr = 0; rr < 2; rr++) {
        va[rr] = *(const float4*)(Abase + (size_t)lrow[rr]*lda + lq[rr]*4);
        vb[rr] = *(const float4*)(Bbase + (size_t)lrow[rr]*lda + lq[rr]*4);
    }
    #pragma unroll
    for (int rr = 0; rr < 2; rr++) {
        sA[0][lq[rr]*4+0][lrow[rr]] = va[rr].x; sA[0][lq[rr]*4+1][lrow[rr]] = va[rr].y;
        sA[0][lq[rr]*4+2][lrow[rr]] = va[rr].z; sA[0][lq[rr]*4+3][lrow[rr]] = va[rr].w;
        sBp[(lq[rr]*4+0)*132 + lrow[rr]] = pk2(vb[rr].x);
        sBp[(lq[rr]*4+1)*132 + lrow[rr]] = pk2(vb[rr].y);
        sBp[(lq[rr]*4+2)*132 + lrow[rr]] = pk2(vb[rr].z);
        sBp[(lq[rr]*4+3)*132 + lrow[rr]] = pk2(vb[rr].w);
    }
    __syncthreads();

    int KT = K >> 4;
    int buf = 0;
    for (int kt = 0; kt < KT; kt++) {
        bool hasNext = (kt + 1 < KT);
        if (hasNext) {
            int koff = (kt + 1) * 16;
            #pragma unroll
            for (int rr = 0; rr < 2; rr++) {
                va[rr] = *(const float4*)(Abase + (size_t)lrow[rr]*lda + koff + lq[rr]*4);
                vb[rr] = *(const float4*)(Bbase + (size_t)lrow[rr]*lda + koff + lq[rr]*4);
            }
        }
        mm16_pk(acc2, sA[buf], sBp + buf*BPK_WORDS, ty, tx);
        if (hasNext) {
            int nb = buf ^ 1;
            unsigned long long* sBn = sBp + nb*BPK_WORDS;
            #pragma unroll
            for (int rr = 0; rr < 2; rr++) {
                sA[nb][lq[rr]*4+0][lrow[rr]] = va[rr].x; sA[nb][lq[rr]*4+1][lrow[rr]] = va[rr].y;
                sA[nb][lq[rr]*4+2][lrow[rr]] = va[rr].z; sA[nb][lq[rr]*4+3][lrow[rr]] = va[rr].w;
                sBn[(lq[rr]*4+0)*132 + lrow[rr]] = pk2(vb[rr].x);
                sBn[(lq[rr]*4+1)*132 + lrow[rr]] = pk2(vb[rr].y);
                sBn[(lq[rr]*4+2)*132 + lrow[rr]] = pk2(vb[rr].z);
                sBn[(lq[rr]*4+3)*132 + lrow[rr]] = pk2(vb[rr].w);
            }
            __syncthreads();
            buf = nb;
        }
    }
    __syncthreads();

    float acc[8][8];
    #pragma unroll
    for (int i2 = 0; i2 < 4; i2++)
        #pragma unroll
        for (int j = 0; j < 8; j++) unpk(acc2[i2][j], acc[2*i2][j], acc[2*i2+1][j]);

    float sqa[8], sqb[8];
    #pragma unroll
    for (int i = 0; i < 8; i++) sqa[i] = g_SQ[bz*1024 + arow0 + ty*8 + i];
    #pragma unroll
    for (int j = 0; j < 8; j++) sqb[j] = g_SQ[bz*1024 + brow0 + tx*8 + j];

    #pragma unroll
    for (int i = 0; i < 8; i++) {
        size_t base = (size_t)(bz*1024 + arow0 + ty*8 + i)*1024 + brow0 + tx*8;
        float4 o0, o1;
        o0.x = 2.f*acc[i][0]-sqb[0]; o0.y = 2.f*acc[i][1]-sqb[1];
        o0.z = 2.f*acc[i][2]-sqb[2]; o0.w = 2.f*acc[i][3]-sqb[3];
        o1.x = 2.f*acc[i][4]-sqb[4]; o1.y = 2.f*acc[i][5]-sqb[5];
        o1.z = 2.f*acc[i][6]-sqb[6]; o1.w = 2.f*acc[i][7]-sqb[7];
        *(float4*)&g_G[base]   = o0;
        *(float4*)&g_G[base+4] = o1;
    }

    if (ib != jb) {
        float (*tA)[132] = sA[0];
        float (*tB)[132] = sA[1];
        #pragma unroll 1
        for (int p = 0; p < 8; p += 2) {
            __syncthreads();
            #pragma unroll
            for (int i = 0; i < 8; i++) {
                tA[tx][ty*8 + i] = 2.f*acc[i][p]   - sqa[i];
                tB[tx][ty*8 + i] = 2.f*acc[i][p+1] - sqa[i];
            }
            __syncthreads();
            int rowIdx = t >> 4;
            int seg    = t & 15;
            size_t b0 = (size_t)(bz*1024 + brow0 + rowIdx*8 + p)*1024 + arow0 + seg*8;
            size_t b1 = (size_t)(bz*1024 + brow0 + rowIdx*8 + p + 1)*1024 + arow0 + seg*8;
            float4 u0 = {tA[rowIdx][seg*8+0], tA[rowIdx][seg*8+1],
                         tA[rowIdx][seg*8+2], tA[rowIdx][seg*8+3]};
            float4 u1 = {tA[rowIdx][seg*8+4], tA[rowIdx][seg*8+5],
                         tA[rowIdx][seg*8+6], tA[rowIdx][seg*8+7]};
            float4 w0 = {tB[rowIdx][seg*8+0], tB[rowIdx][seg*8+1],
                         tB[rowIdx][seg*8+2], tB[rowIdx][seg*8+3]};
            float4 w1 = {tB[rowIdx][seg*8+4], tB[rowIdx][seg*8+5],
                         tB[rowIdx][seg*8+6], tB[rowIdx][seg*8+7]};
            *(float4*)&g_G[b0]   = u0;
            *(float4*)&g_G[b0+4] = u1;
            *(float4*)&g_G[b1]   = w0;
            *(float4*)&g_G[b1+4] = w1;
        }
    }
}

// =======================================================================
// 128x128x16 SGEMM (NT), double-buffered, f32x2 core, packed-B smem.
// EPI 1: plain store to g_Z2. EPI 2: gemm5 fused stats.
// =======================================================================
template<int EPI>
__global__ void __launch_bounds__(256, 2)
sgemm128(const float* __restrict__ A, int lda,
         const float* __restrict__ B, int ldb,
         int K, int N2) {
    __shared__ __align__(16) float sA[2][16][132];
    extern __shared__ __align__(16) unsigned long long sBp[];

    int t  = threadIdx.x;
    int tx = t & 15, ty = t >> 4;
    int arow0 = blockIdx.x*128;
    int n0    = blockIdx.y*128;

    const float* Abase = A + (size_t)arow0 * lda;
    const float* Bbase = B + (size_t)n0 * ldb;

    unsigned long long acc2[4][8];
    #pragma unroll
    for (int i = 0; i < 4; i++)
        #pragma unroll
        for (int j = 0; j < 8; j++) acc2[i][j] = 0ull;

    int lrow[2], lq[2];
    #pragma unroll
    for (int rr = 0; rr < 2; rr++) { int f = t + rr*256; lrow[rr] = f >> 2; lq[rr] = f & 3; }

    float4 va[2], vb[2];
    #pragma unroll
    for (int rr = 0; rr < 2; rr++) {
        va[rr] = *(const float4*)(Abase + (size_t)lrow[rr]*lda + lq[rr]*4);
        vb[rr] = *(const float4*)(Bbase + (size_t)lrow[rr]*ldb + lq[rr]*4);
    }
    #pragma unroll
    for (int rr = 0; rr < 2; rr++) {
        sA[0][lq[rr]*4+0][lrow[rr]] = va[rr].x; sA[0][lq[rr]*4+1][lrow[rr]] = va[rr].y;
        sA[0][lq[rr]*4+2][lrow[rr]] = va[rr].z; sA[0][lq[rr]*4+3][lrow[rr]] = va[rr].w;
        sBp[(lq[rr]*4+0)*132 + lrow[rr]] = pk2(vb[rr].x);
        sBp[(lq[rr]*4+1)*132 + lrow[rr]] = pk2(vb[rr].y);
        sBp[(lq[rr]*4+2)*132 + lrow[rr]] = pk2(vb[rr].z);
        sBp[(lq[rr]*4+3)*132 + lrow[rr]] = pk2(vb[rr].w);
    }
    __syncthreads();

    int KT = K >> 4;
    int buf = 0;
    for (int kt = 0; kt < KT; kt++) {
        bool hasNext = (kt + 1 < KT);
        if (hasNext) {
            int koff = (kt + 1) * 16;
            #pragma unroll
            for (int rr = 0; rr < 2; rr++) {
                va[rr] = *(const float4*)(Abase + (size_t)lrow[rr]*lda + koff + lq[rr]*4);
                vb[rr] = *(const float4*)(Bbase + (size_t)lrow[rr]*ldb + koff + lq[rr]*4);
            }
        }
        mm16_pk(acc2, sA[buf], sBp + buf*BPK_WORDS, ty, tx);
        if (hasNext) {
            int nb = buf ^ 1;
            unsigned long long* sBn = sBp + nb*BPK_WORDS;
            #pragma unroll
            for (int rr = 0; rr < 2; rr++) {
                sA[nb][lq[rr]*4+0][lrow[rr]] = va[rr].x; sA[nb][lq[rr]*4+1][lrow[rr]] = va[rr].y;
                sA[nb][lq[rr]*4+2][lrow[rr]] = va[rr].z; sA[nb][lq[rr]*4+3][lrow[rr]] = va[rr].w;
                sBn[(lq[rr]*4+0)*132 + lrow[rr]] = pk2(vb[rr].x);
                sBn[(lq[rr]*4+1)*132 + lrow[rr]] = pk2(vb[rr].y);
                sBn[(lq[rr]*4+2)*132 + lrow[rr]] = pk2(vb[rr].z);
                sBn[(lq[rr]*4+3)*132 + lrow[rr]] = pk2(vb[rr].w);
            }
            __syncthreads();
            buf = nb;
        }
    }
    __syncthreads();

    float acc[8][8];
    #pragma unroll
    for (int i2 = 0; i2 < 4; i2++)
        #pragma unroll
        for (int j = 0; j < 8; j++) unpk(acc2[i2][j], acc[2*i2][j], acc[2*i2+1][j]);

    if (EPI == 1) {
        #pragma unroll
        for (int i = 0; i < 8; i++) {
            size_t base = (size_t)(arow0 + ty*8 + i)*N2 + n0 + tx*8;
            float4 o0 = {acc[i][0], acc[i][1], acc[i][2], acc[i][3]};
            float4 o1 = {acc[i][4], acc[i][5], acc[i][6], acc[i][7]};
            *(float4*)&g_Z2[base]   = o0;
            *(float4*)&g_Z2[base+4] = o1;
        }
    } else {
        double*   ssum = reinterpret_cast<double*>(&sA[0][0][0]);
        double*   ssq  = ssum + 128;
        unsigned* smx  = reinterpret_cast<unsigned*>(ssq + 128);
        unsigned* smn  = smx + 128;
        if (t < 128) { ssum[t] = 0.0; ssq[t] = 0.0; smx[t] = 0u; smn[t] = 0xFFFFFFFFu; }
        __syncthreads();
        #pragma unroll
        for (int j = 0; j < 8; j++) {
            float s = 0.f, s2 = 0.f, mx = -FLT_MAX, mn = FLT_MAX;
            #pragma unroll
            for (int i = 0; i < 8; i++) {
                float y = acc[i][j];
                s += y; s2 = fmaf(y, y, s2);
                mx = fmaxf(mx, y); mn = fminf(mn, y);
            }
            int col = tx*8 + j;
            atomicAdd(&ssum[col], (double)s);
            atomicAdd(&ssq[col],  (double)s2);
            atomicMax(&smx[col], encf(mx));
            atomicMin(&smn[col], encf(mn));
        }
        __syncthreads();
        if (t < 128) {
            int o = n0 + t;
            int b = arow0 >> 10;
            atomicAdd(&g_SUM[o],   ssum[t]);
            atomicAdd(&g_SUMSQ[o], ssq[t]);
            atomicMax(&g_MXU[b*512 + o], smx[t]);
            atomicMin(&g_MNU[b*512 + o], smn[t]);
        }
    }
}

// ---------------- stage-1 zgemm (C=3) ----------------
template<int C, int N2>
__global__ void zgemm_kernel(const float* __restrict__ X, int ld, int off,
                             const float* __restrict__ W) {
    constexpr int TC = (C < 32) ? C : 32;
    __shared__ float As[64][TC+1];
    __shared__ float Bs[64][TC+1];
    int r0 = blockIdx.x * 64;
    int o0 = blockIdx.y * 64;
    int tx = threadIdx.x & 15, ty = threadIdx.x >> 4;
    float acc[4][4];
    #pragma unroll
    for (int i = 0; i < 4; i++)
        #pragma unroll
        for (int j = 0; j < 4; j++) acc[i][j] = 0.f;
    for (int c0 = 0; c0 < C; c0 += TC) {
        for (int i = threadIdx.x; i < 64*TC; i += 256) {
            int r = i / TC, c = i - r*TC;
            As[r][c] = X[(size_t)(r0 + r)*ld + off + c0 + c];
            Bs[r][c] = W[(size_t)(o0 + r)*C + c0 + c];
        }
        __syncthreads();
        for (int c = 0; c < TC; c++) {
            float av[4], bv[4];
            #pragma unroll
            for (int i = 0; i < 4; i++) { av[i] = As[ty*4+i][c]; bv[i] = Bs[tx*4+i][c]; }
            #pragma unroll
            for (int i = 0; i < 4; i++)
                #pragma unroll
                for (int j = 0; j < 4; j++) acc[i][j] = fmaf(av[i], bv[j], acc[i][j]);
        }
        __syncthreads();
    }
    #pragma unroll
    for (int i = 0; i < 4; i++)
        #pragma unroll
        for (int j = 0; j < 4; j++)
            g_Z2[(size_t)(r0 + ty*4 + i)*N2 + o0 + tx*4 + j] = acc[i][j];
}

// ---------------- warp top-20 pop via redux.sync ----------------
__device__ __forceinline__ unsigned topk_pop(float m1, int s1, int l) {
    unsigned key  = encf(m1);
    unsigned kmax = __reduce_max_sync(0xFFFFFFFFu, key);
    unsigned me   = (unsigned)((s1 << 5) | l);
    unsigned cand = (key == kmax) ? me : 0xFFFFFFFFu;
    return __reduce_min_sync(0xFFFFFFFFu, cand);
}

// ---------------- shared fused topk->gather body ----------------
template<int O>
__device__ __forceinline__ void topk_gather_body(float v[32], int row, int b,
                                                 float* ssum, float* ssq2, int l) {
    float m1 = -FLT_MAX, m2 = -FLT_MAX;
    int s1 = 0, s2v = 0;
    #pragma unroll
    for (int s = 0; s < 32; s++) {
        float xv = v[s];
        if (xv > m2) {
            if (xv > m1) { m2 = m1; s2v = s1; m1 = xv; s1 = s; }
            else         { m2 = xv; s2v = s; }
        }
    }
    bool dirty = false;
    int idxs[KNN];
    for (int j = 0; j < KNN; j++) {
        unsigned win = topk_pop(m1, s1, l);
        idxs[j] = (int)win;
        if (win == (unsigned)((s1 << 5) | l)) {
            #pragma unroll
            for (int s = 0; s < 32; s++) if (s == s1) v[s] = -FLT_MAX;
            if (!dirty) { m1 = m2; s1 = s2v; dirty = true; }
            else {
                m1 = -FLT_MAX; m2 = -FLT_MAX; s1 = 0; s2v = 0;
                #pragma unroll
                for (int s = 0; s < 32; s++) {
                    float xv = v[s];
                    if (xv > m2) {
                        if (xv > m1) { m2 = m1; s2v = s1; m1 = xv; s1 = s; }
                        else         { m2 = xv; s2v = s; }
                    }
                }
                dirty = false;
            }
        }
    }

    const float* Zb = g_Z2 + ((size_t)b << 10) * (2*O);
    const float KF = (float)KNN;
    #pragma unroll 1
    for (int cg = l*4; cg < O; cg += 128) {
        float4 ctr = *(const float4*)&g_Z2[(size_t)row*(2*O) + O + cg];
        float4 mx = {-FLT_MAX, -FLT_MAX, -FLT_MAX, -FLT_MAX};
        float4 mn = { FLT_MAX,  FLT_MAX,  FLT_MAX,  FLT_MAX};
        float4 s  = {0.f, 0.f, 0.f, 0.f};
        float4 s2 = {0.f, 0.f, 0.f, 0.f};
        #pragma unroll
        for (int j = 0; j < KNN; j++) {
            float4 z = *(const float4*)&Zb[(size_t)idxs[j]*(2*O) + cg];
            mx.x = fmaxf(mx.x, z.x); mn.x = fminf(mn.x, z.x); s.x += z.x; s2.x = fmaf(z.x, z.x, s2.x);
            mx.y = fmaxf(mx.y, z.y); mn.y = fminf(mn.y, z.y); s.y += z.y; s2.y = fmaf(z.y, z.y, s2.y);
            mx.z = fmaxf(mx.z, z.z); mn.z = fminf(mn.z, z.z); s.z += z.z; s2.z = fmaf(z.z, z.z, s2.z);
            mx.w = fmaxf(mx.w, z.w); mn.w = fminf(mn.w, z.w); s.w += z.w; s2.w = fmaf(z.w, z.w, s2.w);
        }
        float4 omx = {mx.x + ctr.x, mx.y + ctr.y, mx.z + ctr.z, mx.w + ctr.w};
        float4 omn = {mn.x + ctr.x, mn.y + ctr.y, mn.z + ctr.z, mn.w + ctr.w};
        *(float4*)&g_YMAX[(size_t)row*O + cg] = omx;
        *(float4*)&g_YMIN[(size_t)row*O + cg] = omn;
        atomicAdd(&ssum[cg+0], s.x + KF*ctr.x);
        atomicAdd(&ssum[cg+1], s.y + KF*ctr.y);
        atomicAdd(&ssum[cg+2], s.z + KF*ctr.z);
        atomicAdd(&ssum[cg+3], s.w + KF*ctr.w);
        atomicAdd(&ssq2[cg+0], s2.x + 2.f*ctr.x*s.x + KF*ctr.x*ctr.x);
        atomicAdd(&ssq2[cg+1], s2.y + 2.f*ctr.y*s.y + KF*ctr.y*ctr.y);
        atomicAdd(&ssq2[cg+2], s2.z + 2.f*ctr.z*s.z + KF*ctr.z*ctr.z);
        atomicAdd(&ssq2[cg+3], s2.w + 2.f*ctr.w*s.w + KF*ctr.w*ctr.w);
    }
}

// ---------------- stages 2-4: fused topk(from g_G) + gather ----------------
template<int O>
__global__ void tg_kernel() {
    __shared__ float ssum[O], ssq2[O];
    int n0 = blockIdx.x * 8;
    int b  = n0 >> 10;
    int t  = threadIdx.x, w = t >> 5, l = t & 31;
    if (t < O) { ssum[t] = 0.f; ssq2[t] = 0.f; }
    __syncthreads();

    int row = n0 + w;
    const float* grow = g_G + (size_t)row * NN;
    float v[32];
    #pragma unroll
    for (int s = 0; s < 32; s++) v[s] = grow[s*32 + l];

    topk_gather_body<O>(v, row, b, ssum, ssq2, l);

    __syncthreads();
    if (t < O) {
        atomicAdd(&g_SUM[t],   (double)ssum[t]);
        atomicAdd(&g_SUMSQ[t], (double)ssq2[t]);
    }
}

// ---------------- stage 1: fused distances + topk + gather (O=64) ----------------
__global__ void tg1_kernel(const float* __restrict__ x) {
    __shared__ float spx[1024], spy[1024], spz[1024], ssq[1024];
    __shared__ float ssum[64], ssq2[64];
    int n0 = blockIdx.x * 8;
    int b  = n0 >> 10;
    int t  = threadIdx.x, w = t >> 5, l = t & 31;
    const float* xb = x + (size_t)b * 3072;
    if (t < 64) { ssum[t] = 0.f; ssq2[t] = 0.f; }
    for (int m = t; m < 1024; m += 256) {
        float px = xb[m*3], py = xb[m*3+1], pz = xb[m*3+2];
        spx[m] = px; spy[m] = py; spz[m] = pz;
        ssq[m] = fmaf(px, px, fmaf(py, py, pz*pz));
    }
    __syncthreads();

    int ln = (n0 & 1023) + w;
    float dnx = 2.f*spx[ln], dny = 2.f*spy[ln], dnz = 2.f*spz[ln];
    float v[32];
    #pragma unroll
    for (int s = 0; s < 32; s++) {
        int m = s*32 + l;
        v[s] = fmaf(dnx, spx[m], fmaf(dny, spy[m], fmaf(dnz, spz[m], -ssq[m])));
    }

    topk_gather_body<64>(v, n0 + w, b, ssum, ssq2, l);

    __syncthreads();
    if (t < 64) {
        atomicAdd(&g_SUM[t],   (double)ssum[t]);
        atomicAdd(&g_SUMSQ[t], (double)ssq2[t]);
    }
}

// ---------------- BN affine coeffs (reciprocal-mult); self-resets ----------------
__global__ void stats_kernel(const float* __restrict__ g, const float* __restrict__ beta,
                             double invCnt, int O, int resetMM) {
    int o = threadIdx.x;
    if (resetMM) {
        for (int i = o; i < BB*512; i += 512) { g_MXU[i] = 0u; g_MNU[i] = 0xFFFFFFFFu; }
    }
    if (o >= O) return;
    double m   = g_SUM[o]   * invCnt;
    double var = g_SUMSQ[o] * invCnt - m*m;
    float a = g[o] / sqrtf((float)var + 1e-5f);
    g_A[o]  = a;
    g_Cc[o] = beta[o] - (float)m * a;
    g_SUM[o] = 0.0; g_SUMSQ[o] = 0.0;
}

// ---------------- apply norm+lrelu, write concat features + per-point sq ----------------
template<int O>
__global__ void apply_kernel(int outOff) {
    constexpr int PPB = 256 / O;
    __shared__ float psq[PPB > 0 ? PPB : 1];
    int t = threadIdx.x;
    int p = t / O;
    int o = t - p*O;
    int n = blockIdx.x * PPB + p;
    size_t i = (size_t)n*O + o;

    if (t < PPB) psq[t] = 0.f;
    __syncthreads();

    float a = g_A[o], c = g_Cc[o];
    float sel = (a >= 0.f) ? g_YMAX[i] : g_YMIN[i];
    float v = fmaf(a, sel, c);
    v = (v >= 0.f) ? v : 0.2f*v;
    g_FEAT[(size_t)n*512 + outOff + o] = v;

    float s = v*v;
    #pragma unroll
    for (int sh = 16; sh; sh >>= 1) s += __shfl_down_sync(0xFFFFFFFFu, s, sh);
    if ((t & 31) == 0) atomicAdd(&psq[p], s);
    __syncthreads();
    if (o == 0) g_SQ[n] = psq[p];
}

// ---------------- final norm + global max + embedding ----------------
__global__ void emb_kernel(const float* __restrict__ wemb, float* __restrict__ out) {
    __shared__ float feat[512];
    int b = blockIdx.x, t = threadIdx.x;
    for (int o = t; o < 512; o += 256) {
        float a = g_A[o], c = g_Cc[o];
        float sel = (a >= 0.f) ? decf(g_MXU[b*512 + o]) : decf(g_MNU[b*512 + o]);
        float v = fmaf(a, sel, c);
        feat[o] = (v >= 0.f) ? v : 0.2f*v;
    }
    __syncthreads();
    const float* wr = wemb + (size_t)t * 512;
    float s = 0.f;
    for (int c = 0; c < 512; c++) s = fmaf(wr[c], feat[c], s);
    out[b*256 + t] = s;
}

// ---------------- host orchestration ----------------
static cudaStream_t g_sideStream = 0;
static cudaEvent_t  g_evFork = 0, g_evJoin = 0;
static bool g_attrDone = false;
static const double INV_CNT_K = 1.0 / (double)(BB*NN*KNN);
static const double INV_CNT_N = 1.0 / (double)(BB*NN);

template<int C, int O>
static void run_edge_big(const float* feat, int off, const float* wcat,
                         const float* g, const float* beta, int resetMM, int outOff) {
    dim3 gg(36, 1, BB);
    dim3 zg(64, (2*O)/128, 1);
    if (g_sideStream) {
        cudaEventRecord(g_evFork, 0);
        cudaStreamWaitEvent(g_sideStream, g_evFork, 0);
        sgemm128<1><<<zg, 256, BPK_BYTES, g_sideStream>>>(feat + off, 512, wcat, C, C, 2*O);
        cudaEventRecord(g_evJoin, g_sideStream);
        gram_sym<<<gg, 256, BPK_BYTES>>>(feat + off, 512, C);
        cudaStreamWaitEvent(0, g_evJoin, 0);
    } else {
        gram_sym<<<gg, 256, BPK_BYTES>>>(feat + off, 512, C);
        sgemm128<1><<<zg, 256, BPK_BYTES>>>(feat + off, 512, wcat, C, C, 2*O);
    }
    tg_kernel<O><<<BB*NN/8, 256>>>();
    stats_kernel<<<1, 512>>>(g, beta, INV_CNT_K, O, resetMM);
    apply_kernel<O><<<BB*NN/(256/O), 256>>>(outOff);
}

extern "C" void kernel_launch(void* const* d_in, const int* in_sizes, int n_in,
                              void* d_out, int out_size) {
    (void)in_sizes; (void)n_in; (void)out_size;
    const float* x    = (const float*)d_in[0];
    const float* w1   = (const float*)d_in[1];
    const float* g1   = (const float*)d_in[2];
    const float* b1   = (const float*)d_in[3];
    const float* w2   = (const float*)d_in[4];
    const float* g2   = (const float*)d_in[5];
    const float* b2   = (const float*)d_in[6];
    const float* w3   = (const float*)d_in[7];
    const float* g3   = (const float*)d_in[8];
    const float* b3   = (const float*)d_in[9];
    const float* w4   = (const float*)d_in[10];
    const float* g4   = (const float*)d_in[11];
    const float* b4   = (const float*)d_in[12];
    const float* w5   = (const float*)d_in[13];
    const float* g5   = (const float*)d_in[14];
    const float* b5   = (const float*)d_in[15];
    const float* wemb = (const float*)d_in[16];
    float* out = (float*)d_out;

    float *feat, *wcat;
    cudaGetSymbolAddress((void**)&feat, g_FEAT);
    cudaGetSymbolAddress((void**)&wcat, g_WCAT);

    if (!g_attrDone) {
        cudaFuncSetAttribute(gram_sym,    cudaFuncAttributeMaxDynamicSharedMemorySize, BPK_BYTES);
        cudaFuncSetAttribute(sgemm128<1>, cudaFuncAttributeMaxDynamicSharedMemorySize, BPK_BYTES);
        cudaFuncSetAttribute(sgemm128<2>, cudaFuncAttributeMaxDynamicSharedMemorySize, BPK_BYTES);
        g_attrDone = true;
    }
    if (!g_sideStream) {
        cudaStream_t s = 0;
        cudaEvent_t e1 = 0, e2 = 0;
        if (cudaStreamCreateWithFlags(&s, cudaStreamNonBlocking) == cudaSuccess &&
            cudaEventCreateWithFlags(&e1, cudaEventDisableTiming) == cudaSuccess &&
            cudaEventCreateWithFlags(&e2, cudaEventDisableTiming) == cudaSuccess) {
            g_sideStream = s; g_evFork = e1; g_evJoin = e2;
        }
    }

    prep_kernel<<<(90496 + 255)/256, 256>>>(w1, w2, w3, w4);

    // ---- stage 1 (C=3): zgemm, fused distances+topk+gather ----
    dim3 zg1(BB*NN/64, 2);
    zgemm_kernel<3, 128><<<zg1, 256>>>(x, 3, 0, wcat);
    tg1_kernel<<<BB*NN/8, 256>>>(x);
    stats_kernel<<<1, 512>>>(g1, b1, INV_CNT_K, 64, 0);
    apply_kernel<64><<<BB*NN/4, 256>>>(0);

    // ---- stages 2-4: gram || zgemm (fork), fused topk-gather ----
    run_edge_big<64,  64 >(feat, 0,   wcat + 384,   g2, b2, 0, 64);
    run_edge_big<64,  128>(feat, 64,  wcat + 8576,  g3, b3, 0, 128);
    run_edge_big<128, 256>(feat, 128, wcat + 24960, g4, b4, 1, 256);

    // ---- final conv 512x512 fused with stats + max/min ----
    dim3 g5g(64, 4, 1);
    sgemm128<2><<<g5g, 256, BPK_BYTES>>>(feat, 512, w5, 512, 512, 0);
    stats_kernel<<<1, 512>>>(g5, b5, INV_CNT_N, 512, 0);
    emb_kernel<<<BB, 256>>>(wemb, out);
}

// round 17
// speedup vs baseline: 1.8030x; 1.8030x over previous
#include <cuda_runtime.h>
#include <math.h>
#include <float.h>

#define BB 8
#define NN 1024
#define KNN 20

// ---------------- static device scratch ----------------
__device__ float    g_G[(size_t)BB*NN*NN];        // pairwise 2*dot - sq[m]
__device__ float    g_SQ[BB*NN];
__device__ float    g_Z2[(size_t)BB*NN*512];      // [bn][2O]: Zn | Zc
__device__ float    g_FEAT[(size_t)BB*NN*512];    // concat features (bn, c)
__device__ float    g_YMAX[(size_t)BB*NN*256];
__device__ float    g_YMIN[(size_t)BB*NN*256];
__device__ double   g_SUM[512];
__device__ double   g_SUMSQ[512];
__device__ float    g_A[512];
__device__ float    g_Cc[512];
__device__ float    g_WCAT[90496];                // [Wn ; Wc-Wn] per block
__device__ unsigned g_MXU[BB*512];
__device__ unsigned g_MNU[BB*512];

__device__ __forceinline__ unsigned encf(float f) {
    unsigned b = __float_as_uint(f);
    return (b & 0x80000000u) ? ~b : (b | 0x80000000u);
}
__device__ __forceinline__ float decf(unsigned u) {
    return __uint_as_float((u & 0x80000000u) ? (u & 0x7FFFFFFFu) : ~u);
}

// ---- packed f32x2 helpers (Blackwell dual-rate FP32) ----
__device__ __forceinline__ unsigned long long pk2(float v) {
    unsigned long long r;
    asm("mov.b64 %0, {%1,%1};" : "=l"(r) : "f"(v));
    return r;
}
__device__ __forceinline__ void ffma2(unsigned long long &d,
                                      unsigned long long a, unsigned long long b) {
    asm("fma.rn.f32x2 %0, %1, %2, %0;" : "+l"(d) : "l"(a), "l"(b));
}
__device__ __forceinline__ void unpk(unsigned long long v, float &lo, float &hi) {
    asm("mov.b64 {%0,%1}, %2;" : "=f"(lo), "=f"(hi) : "l"(v));
}

// WCAT offsets: b1:0 (128x3), b2:384 (128x64), b3:8576 (256x64), b4:24960 (512x128)
__global__ void prep_kernel(const float* __restrict__ w1, const float* __restrict__ w2,
                            const float* __restrict__ w3, const float* __restrict__ w4) {
    int t = blockIdx.x * blockDim.x + threadIdx.x;
    if (t < 384) {
        int r = t/3, c = t%3;
        g_WCAT[t] = (r < 64) ? w1[r*6 + c] : (w1[(r-64)*6 + 3 + c] - w1[(r-64)*6 + c]);
        return;
    }
    int u = t - 384;
    if (u < 8192) {
        int r = u/64, c = u%64;
        g_WCAT[384 + u] = (r < 64) ? w2[r*128 + c] : (w2[(r-64)*128 + 64 + c] - w2[(r-64)*128 + c]);
        return;
    }
    u -= 8192;
    if (u < 16384) {
        int r = u/64, c = u%64;
        g_WCAT[8576 + u] = (r < 128) ? w3[r*128 + c] : (w3[(r-128)*128 + 64 + c] - w3[(r-128)*128 + c]);
        return;
    }
    u -= 16384;
    if (u < 65536) {
        int r = u/128, c = u%128;
        g_WCAT[24960 + u] = (r < 256) ? w4[r*256 + c] : (w4[(r-256)*256 + 128 + c] - w4[(r-256)*256 + c]);
        return;
    }
}

// ---- shared packed inner product over one 16-k smem tile ----
__device__ __forceinline__ void mm16_f32x2(unsigned long long acc2[4][8],
                                           const float (*sAk)[132], const float (*sBk)[132],
                                           int ty, int tx) {
    #pragma unroll
    for (int k = 0; k < 16; k++) {
        const ulonglong2* pa = (const ulonglong2*)&sAk[k][ty*8];
        ulonglong2 A01 = pa[0], A23 = pa[1];
        unsigned long long a2[4] = {A01.x, A01.y, A23.x, A23.y};
        float4 b0 = *(const float4*)&sBk[k][tx*8];
        float4 b1 = *(const float4*)&sBk[k][tx*8 + 4];
        unsigned long long bb[8] = {pk2(b0.x), pk2(b0.y), pk2(b0.z), pk2(b0.w),
                                    pk2(b1.x), pk2(b1.y), pk2(b1.z), pk2(b1.w)};
        #pragma unroll
        for (int i2 = 0; i2 < 4; i2++)
            #pragma unroll
            for (int j = 0; j < 8; j++)
                ffma2(acc2[i2][j], a2[i2], bb[j]);
    }
}

// =======================================================================
// Symmetric gram, double-buffered, f32x2 core.
// =======================================================================
__global__ void __launch_bounds__(256, 2)
gram_sym(const float* __restrict__ A, int lda, int K) {
    __shared__ __align__(16) float sA[2][16][132];
    __shared__ __align__(16) float sB[2][16][132];

    int t  = threadIdx.x;
    int tx = t & 15, ty = t >> 4;
    int bz = blockIdx.z;

    int idx = blockIdx.x;
    int ib = 0;
    while (idx >= 8 - ib) { idx -= 8 - ib; ib++; }
    int jb = ib + idx;

    int arow0 = ib * 128;
    int brow0 = jb * 128;
    const float* Abase = A + (size_t)(bz*1024 + arow0) * lda;
    const float* Bbase = A + (size_t)(bz*1024 + brow0) * lda;

    unsigned long long acc2[4][8];
    #pragma unroll
    for (int i = 0; i < 4; i++)
        #pragma unroll
        for (int j = 0; j < 8; j++) acc2[i][j] = 0ull;

    int lrow[2], lq[2];
    #pragma unroll
    for (int rr = 0; rr < 2; rr++) { int f = t + rr*256; lrow[rr] = f >> 2; lq[rr] = f & 3; }

    float4 va[2], vb[2];
    #pragma unroll
    for (int rr = 0; rr < 2; rr++) {
        va[rr] = *(const float4*)(Abase + (size_t)lrow[rr]*lda + lq[rr]*4);
        vb[rr] = *(const float4*)(Bbase + (size_t)lrow[rr]*lda + lq[rr]*4);
    }
    #pragma unroll
    for (int rr = 0; rr < 2; rr++) {
        sA[0][lq[rr]*4+0][lrow[rr]] = va[rr].x; sA[0][lq[rr]*4+1][lrow[rr]] = va[rr].y;
        sA[0][lq[rr]*4+2][lrow[rr]] = va[rr].z; sA[0][lq[rr]*4+3][lrow[rr]] = va[rr].w;
        sB[0][lq[rr]*4+0][lrow[rr]] = vb[rr].x; sB[0][lq[rr]*4+1][lrow[rr]] = vb[rr].y;
        sB[0][lq[rr]*4+2][lrow[rr]] = vb[rr].z; sB[0][lq[rr]*4+3][lrow[rr]] = vb[rr].w;
    }
    __syncthreads();

    int KT = K >> 4;
    int buf = 0;
    for (int kt = 0; kt < KT; kt++) {
        bool hasNext = (kt + 1 < KT);
        if (hasNext) {
            int koff = (kt + 1) * 16;
            #pragma unroll
            for (int rr = 0; rr < 2; rr++) {
                va[rr] = *(const float4*)(Abase + (size_t)lrow[rr]*lda + koff + lq[rr]*4);
                vb[rr] = *(const float4*)(Bbase + (size_t)lrow[rr]*lda + koff + lq[rr]*4);
            }
        }
        mm16_f32x2(acc2, sA[buf], sB[buf], ty, tx);
        if (hasNext) {
            int nb = buf ^ 1;
            #pragma unroll
            for (int rr = 0; rr < 2; rr++) {
                sA[nb][lq[rr]*4+0][lrow[rr]] = va[rr].x; sA[nb][lq[rr]*4+1][lrow[rr]] = va[rr].y;
                sA[nb][lq[rr]*4+2][lrow[rr]] = va[rr].z; sA[nb][lq[rr]*4+3][lrow[rr]] = va[rr].w;
                sB[nb][lq[rr]*4+0][lrow[rr]] = vb[rr].x; sB[nb][lq[rr]*4+1][lrow[rr]] = vb[rr].y;
                sB[nb][lq[rr]*4+2][lrow[rr]] = vb[rr].z; sB[nb][lq[rr]*4+3][lrow[rr]] = vb[rr].w;
            }
            __syncthreads();
            buf = nb;
        }
    }
    __syncthreads();

    float acc[8][8];
    #pragma unroll
    for (int i2 = 0; i2 < 4; i2++)
        #pragma unroll
        for (int j = 0; j < 8; j++) unpk(acc2[i2][j], acc[2*i2][j], acc[2*i2+1][j]);

    float sqa[8], sqb[8];
    #pragma unroll
    for (int i = 0; i < 8; i++) sqa[i] = g_SQ[bz*1024 + arow0 + ty*8 + i];
    #pragma unroll
    for (int j = 0; j < 8; j++) sqb[j] = g_SQ[bz*1024 + brow0 + tx*8 + j];

    #pragma unroll
    for (int i = 0; i < 8; i++) {
        size_t base = (size_t)(bz*1024 + arow0 + ty*8 + i)*1024 + brow0 + tx*8;
        float4 o0, o1;
        o0.x = 2.f*acc[i][0]-sqb[0]; o0.y = 2.f*acc[i][1]-sqb[1];
        o0.z = 2.f*acc[i][2]-sqb[2]; o0.w = 2.f*acc[i][3]-sqb[3];
        o1.x = 2.f*acc[i][4]-sqb[4]; o1.y = 2.f*acc[i][5]-sqb[5];
        o1.z = 2.f*acc[i][6]-sqb[6]; o1.w = 2.f*acc[i][7]-sqb[7];
        *(float4*)&g_G[base]   = o0;
        *(float4*)&g_G[base+4] = o1;
    }

    if (ib != jb) {
        float (*tA)[132] = sA[0];
        float (*tB)[132] = sB[0];
        #pragma unroll 1
        for (int p = 0; p < 8; p += 2) {
            __syncthreads();
            #pragma unroll
            for (int i = 0; i < 8; i++) {
                tA[tx][ty*8 + i] = 2.f*acc[i][p]   - sqa[i];
                tB[tx][ty*8 + i] = 2.f*acc[i][p+1] - sqa[i];
            }
            __syncthreads();
            int rowIdx = t >> 4;
            int seg    = t & 15;
            size_t b0 = (size_t)(bz*1024 + brow0 + rowIdx*8 + p)*1024 + arow0 + seg*8;
            size_t b1 = (size_t)(bz*1024 + brow0 + rowIdx*8 + p + 1)*1024 + arow0 + seg*8;
            float4 u0 = {tA[rowIdx][seg*8+0], tA[rowIdx][seg*8+1],
                         tA[rowIdx][seg*8+2], tA[rowIdx][seg*8+3]};
            float4 u1 = {tA[rowIdx][seg*8+4], tA[rowIdx][seg*8+5],
                         tA[rowIdx][seg*8+6], tA[rowIdx][seg*8+7]};
            float4 w0 = {tB[rowIdx][seg*8+0], tB[rowIdx][seg*8+1],
                         tB[rowIdx][seg*8+2], tB[rowIdx][seg*8+3]};
            float4 w1 = {tB[rowIdx][seg*8+4], tB[rowIdx][seg*8+5],
                         tB[rowIdx][seg*8+6], tB[rowIdx][seg*8+7]};
            *(float4*)&g_G[b0]   = u0;
            *(float4*)&g_G[b0+4] = u1;
            *(float4*)&g_G[b1]   = w0;
            *(float4*)&g_G[b1+4] = w1;
        }
    }
}

// =======================================================================
// 128x128x16 SGEMM (NT), double-buffered, f32x2 core.
// EPI 1: plain store to g_Z2. EPI 2: gemm5 fused stats.
// =======================================================================
template<int EPI>
__global__ void __launch_bounds__(256, 2)
sgemm128(const float* __restrict__ A, int lda,
         const float* __restrict__ B, int ldb,
         int K, int N2) {
    __shared__ __align__(16) float sA[2][16][132];
    __shared__ __align__(16) float sB[2][16][132];

    int t  = threadIdx.x;
    int tx = t & 15, ty = t >> 4;
    int arow0 = blockIdx.x*128;
    int n0    = blockIdx.y*128;

    const float* Abase = A + (size_t)arow0 * lda;
    const float* Bbase = B + (size_t)n0 * ldb;

    unsigned long long acc2[4][8];
    #pragma unroll
    for (int i = 0; i < 4; i++)
        #pragma unroll
        for (int j = 0; j < 8; j++) acc2[i][j] = 0ull;

    int lrow[2], lq[2];
    #pragma unroll
    for (int rr = 0; rr < 2; rr++) { int f = t + rr*256; lrow[rr] = f >> 2; lq[rr] = f & 3; }

    float4 va[2], vb[2];
    #pragma unroll
    for (int rr = 0; rr < 2; rr++) {
        va[rr] = *(const float4*)(Abase + (size_t)lrow[rr]*lda + lq[rr]*4);
        vb[rr] = *(const float4*)(Bbase + (size_t)lrow[rr]*ldb + lq[rr]*4);
    }
    #pragma unroll
    for (int rr = 0; rr < 2; rr++) {
        sA[0][lq[rr]*4+0][lrow[rr]] = va[rr].x; sA[0][lq[rr]*4+1][lrow[rr]] = va[rr].y;
        sA[0][lq[rr]*4+2][lrow[rr]] = va[rr].z; sA[0][lq[rr]*4+3][lrow[rr]] = va[rr].w;
        sB[0][lq[rr]*4+0][lrow[rr]] = vb[rr].x; sB[0][lq[rr]*4+1][lrow[rr]] = vb[rr].y;
        sB[0][lq[rr]*4+2][lrow[rr]] = vb[rr].z; sB[0][lq[rr]*4+3][lrow[rr]] = vb[rr].w;
    }
    __syncthreads();

    int KT = K >> 4;
    int buf = 0;
    for (int kt = 0; kt < KT; kt++) {
        bool hasNext = (kt + 1 < KT);
        if (hasNext) {
            int koff = (kt + 1) * 16;
            #pragma unroll
            for (int rr = 0; rr < 2; rr++) {
                va[rr] = *(const float4*)(Abase + (size_t)lrow[rr]*lda + koff + lq[rr]*4);
                vb[rr] = *(const float4*)(Bbase + (size_t)lrow[rr]*ldb + koff + lq[rr]*4);
            }
        }
        mm16_f32x2(acc2, sA[buf], sB[buf], ty, tx);
        if (hasNext) {
            int nb = buf ^ 1;
            #pragma unroll
            for (int rr = 0; rr < 2; rr++) {
                sA[nb][lq[rr]*4+0][lrow[rr]] = va[rr].x; sA[nb][lq[rr]*4+1][lrow[rr]] = va[rr].y;
                sA[nb][lq[rr]*4+2][lrow[rr]] = va[rr].z; sA[nb][lq[rr]*4+3][lrow[rr]] = va[rr].w;
                sB[nb][lq[rr]*4+0][lrow[rr]] = vb[rr].x; sB[nb][lq[rr]*4+1][lrow[rr]] = vb[rr].y;
                sB[nb][lq[rr]*4+2][lrow[rr]] = vb[rr].z; sB[nb][lq[rr]*4+3][lrow[rr]] = vb[rr].w;
            }
            __syncthreads();
            buf = nb;
        }
    }
    __syncthreads();

    float acc[8][8];
    #pragma unroll
    for (int i2 = 0; i2 < 4; i2++)
        #pragma unroll
        for (int j = 0; j < 8; j++) unpk(acc2[i2][j], acc[2*i2][j], acc[2*i2+1][j]);

    if (EPI == 1) {
        #pragma unroll
        for (int i = 0; i < 8; i++) {
            size_t base = (size_t)(arow0 + ty*8 + i)*N2 + n0 + tx*8;
            float4 o0 = {acc[i][0], acc[i][1], acc[i][2], acc[i][3]};
            float4 o1 = {acc[i][4], acc[i][5], acc[i][6], acc[i][7]};
            *(float4*)&g_Z2[base]   = o0;
            *(float4*)&g_Z2[base+4] = o1;
        }
    } else {
        double*   ssum = reinterpret_cast<double*>(&sA[0][0][0]);
        double*   ssq  = ssum + 128;
        unsigned* smx  = reinterpret_cast<unsigned*>(ssq + 128);
        unsigned* smn  = smx + 128;
        if (t < 128) { ssum[t] = 0.0; ssq[t] = 0.0; smx[t] = 0u; smn[t] = 0xFFFFFFFFu; }
        __syncthreads();
        #pragma unroll
        for (int j = 0; j < 8; j++) {
            float s = 0.f, s2 = 0.f, mx = -FLT_MAX, mn = FLT_MAX;
            #pragma unroll
            for (int i = 0; i < 8; i++) {
                float y = acc[i][j];
                s += y; s2 = fmaf(y, y, s2);
                mx = fmaxf(mx, y); mn = fminf(mn, y);
            }
            int col = tx*8 + j;
            atomicAdd(&ssum[col], (double)s);
            atomicAdd(&ssq[col],  (double)s2);
            atomicMax(&smx[col], encf(mx));
            atomicMin(&smn[col], encf(mn));
        }
        __syncthreads();
        if (t < 128) {
            int o = n0 + t;
            int b = arow0 >> 10;
            atomicAdd(&g_SUM[o],   ssum[t]);
            atomicAdd(&g_SUMSQ[o], ssq[t]);
            atomicMax(&g_MXU[b*512 + o], smx[t]);
            atomicMin(&g_MNU[b*512 + o], smn[t]);
        }
    }
}

// ---------------- stage-1 zgemm (C=3) ----------------
template<int C, int N2>
__global__ void zgemm_kernel(const float* __restrict__ X, int ld, int off,
                             const float* __restrict__ W) {
    constexpr int TC = (C < 32) ? C : 32;
    __shared__ float As[64][TC+1];
    __shared__ float Bs[64][TC+1];
    int r0 = blockIdx.x * 64;
    int o0 = blockIdx.y * 64;
    int tx = threadIdx.x & 15, ty = threadIdx.x >> 4;
    float acc[4][4];
    #pragma unroll
    for (int i = 0; i < 4; i++)
        #pragma unroll
        for (int j = 0; j < 4; j++) acc[i][j] = 0.f;
    for (int c0 = 0; c0 < C; c0 += TC) {
        for (int i = threadIdx.x; i < 64*TC; i += 256) {
            int r = i / TC, c = i - r*TC;
            As[r][c] = X[(size_t)(r0 + r)*ld + off + c0 + c];
            Bs[r][c] = W[(size_t)(o0 + r)*C + c0 + c];
        }
        __syncthreads();
        for (int c = 0; c < TC; c++) {
            float av[4], bv[4];
            #pragma unroll
            for (int i = 0; i < 4; i++) { av[i] = As[ty*4+i][c]; bv[i] = Bs[tx*4+i][c]; }
            #pragma unroll
            for (int i = 0; i < 4; i++)
                #pragma unroll
                for (int j = 0; j < 4; j++) acc[i][j] = fmaf(av[i], bv[j], acc[i][j]);
        }
        __syncthreads();
    }
    #pragma unroll
    for (int i = 0; i < 4; i++)
        #pragma unroll
        for (int j = 0; j < 4; j++)
            g_Z2[(size_t)(r0 + ty*4 + i)*N2 + o0 + tx*4 + j] = acc[i][j];
}

// ---------------- warp top-20 pop via redux.sync ----------------
__device__ __forceinline__ unsigned topk_pop(float m1, int s1, int l) {
    unsigned key  = encf(m1);
    unsigned kmax = __reduce_max_sync(0xFFFFFFFFu, key);
    unsigned me   = (unsigned)((s1 << 5) | l);
    unsigned cand = (key == kmax) ? me : 0xFFFFFFFFu;
    return __reduce_min_sync(0xFFFFFFFFu, cand);
}

// ---------------- shared fused topk->gather body ----------------
template<int O>
__device__ __forceinline__ void topk_gather_body(float v[32], int row, int b,
                                                 float* ssum, float* ssq2, int l) {
    float m1 = -FLT_MAX, m2 = -FLT_MAX;
    int s1 = 0, s2v = 0;
    #pragma unroll
    for (int s = 0; s < 32; s++) {
        float xv = v[s];
        if (xv > m2) {
            if (xv > m1) { m2 = m1; s2v = s1; m1 = xv; s1 = s; }
            else         { m2 = xv; s2v = s; }
        }
    }
    bool dirty = false;
    int idxs[KNN];
    for (int j = 0; j < KNN; j++) {
        unsigned win = topk_pop(m1, s1, l);
        idxs[j] = (int)win;
        if (win == (unsigned)((s1 << 5) | l)) {
            #pragma unroll
            for (int s = 0; s < 32; s++) if (s == s1) v[s] = -FLT_MAX;
            if (!dirty) { m1 = m2; s1 = s2v; dirty = true; }
            else {
                m1 = -FLT_MAX; m2 = -FLT_MAX; s1 = 0; s2v = 0;
                #pragma unroll
                for (int s = 0; s < 32; s++) {
                    float xv = v[s];
                    if (xv > m2) {
                        if (xv > m1) { m2 = m1; s2v = s1; m1 = xv; s1 = s; }
                        else         { m2 = xv; s2v = s; }
                    }
                }
                dirty = false;
            }
        }
    }

    const float* Zb = g_Z2 + ((size_t)b << 10) * (2*O);
    const float KF = (float)KNN;
    #pragma unroll 1
    for (int cg = l*4; cg < O; cg += 128) {
        float4 ctr = *(const float4*)&g_Z2[(size_t)row*(2*O) + O + cg];
        float4 mx = {-FLT_MAX, -FLT_MAX, -FLT_MAX, -FLT_MAX};
        float4 mn = { FLT_MAX,  FLT_MAX,  FLT_MAX,  FLT_MAX};
        float4 s  = {0.f, 0.f, 0.f, 0.f};
        float4 s2 = {0.f, 0.f, 0.f, 0.f};
        #pragma unroll
        for (int j = 0; j < KNN; j++) {
            float4 z = *(const float4*)&Zb[(size_t)idxs[j]*(2*O) + cg];
            mx.x = fmaxf(mx.x, z.x); mn.x = fminf(mn.x, z.x); s.x += z.x; s2.x = fmaf(z.x, z.x, s2.x);
            mx.y = fmaxf(mx.y, z.y); mn.y = fminf(mn.y, z.y); s.y += z.y; s2.y = fmaf(z.y, z.y, s2.y);
            mx.z = fmaxf(mx.z, z.z); mn.z = fminf(mn.z, z.z); s.z += z.z; s2.z = fmaf(z.z, z.z, s2.z);
            mx.w = fmaxf(mx.w, z.w); mn.w = fminf(mn.w, z.w); s.w += z.w; s2.w = fmaf(z.w, z.w, s2.w);
        }
        float4 omx = {mx.x + ctr.x, mx.y + ctr.y, mx.z + ctr.z, mx.w + ctr.w};
        float4 omn = {mn.x + ctr.x, mn.y + ctr.y, mn.z + ctr.z, mn.w + ctr.w};
        *(float4*)&g_YMAX[(size_t)row*O + cg] = omx;
        *(float4*)&g_YMIN[(size_t)row*O + cg] = omn;
        atomicAdd(&ssum[cg+0], s.x + KF*ctr.x);
        atomicAdd(&ssum[cg+1], s.y + KF*ctr.y);
        atomicAdd(&ssum[cg+2], s.z + KF*ctr.z);
        atomicAdd(&ssum[cg+3], s.w + KF*ctr.w);
        atomicAdd(&ssq2[cg+0], s2.x + 2.f*ctr.x*s.x + KF*ctr.x*ctr.x);
        atomicAdd(&ssq2[cg+1], s2.y + 2.f*ctr.y*s.y + KF*ctr.y*ctr.y);
        atomicAdd(&ssq2[cg+2], s2.z + 2.f*ctr.z*s.z + KF*ctr.z*ctr.z);
        atomicAdd(&ssq2[cg+3], s2.w + 2.f*ctr.w*s.w + KF*ctr.w*ctr.w);
    }
}

// ---------------- stages 2-4: fused topk(from g_G) + gather ----------------
template<int O>
__global__ void tg_kernel() {
    __shared__ float ssum[O], ssq2[O];
    int n0 = blockIdx.x * 8;
    int b  = n0 >> 10;
    int t  = threadIdx.x, w = t >> 5, l = t & 31;
    if (t < O) { ssum[t] = 0.f; ssq2[t] = 0.f; }
    __syncthreads();

    int row = n0 + w;
    const float* grow = g_G + (size_t)row * NN;
    float v[32];
    #pragma unroll
    for (int s = 0; s < 32; s++) v[s] = grow[s*32 + l];

    topk_gather_body<O>(v, row, b, ssum, ssq2, l);

    __syncthreads();
    if (t < O) {
        atomicAdd(&g_SUM[t],   (double)ssum[t]);
        atomicAdd(&g_SUMSQ[t], (double)ssq2[t]);
    }
}

// ---------------- stage 1: fused distances + topk + gather (O=64) ----------------
__global__ void tg1_kernel(const float* __restrict__ x) {
    __shared__ float spx[1024], spy[1024], spz[1024], ssq[1024];
    __shared__ float ssum[64], ssq2[64];
    int n0 = blockIdx.x * 8;
    int b  = n0 >> 10;
    int t  = threadIdx.x, w = t >> 5, l = t & 31;
    const float* xb = x + (size_t)b * 3072;
    if (t < 64) { ssum[t] = 0.f; ssq2[t] = 0.f; }
    for (int m = t; m < 1024; m += 256) {
        float px = xb[m*3], py = xb[m*3+1], pz = xb[m*3+2];
        spx[m] = px; spy[m] = py; spz[m] = pz;
        ssq[m] = fmaf(px, px, fmaf(py, py, pz*pz));
    }
    __syncthreads();

    int ln = (n0 & 1023) + w;
    float dnx = 2.f*spx[ln], dny = 2.f*spy[ln], dnz = 2.f*spz[ln];
    float v[32];
    #pragma unroll
    for (int s = 0; s < 32; s++) {
        int m = s*32 + l;
        v[s] = fmaf(dnx, spx[m], fmaf(dny, spy[m], fmaf(dnz, spz[m], -ssq[m])));
    }

    topk_gather_body<64>(v, n0 + w, b, ssum, ssq2, l);

    __syncthreads();
    if (t < 64) {
        atomicAdd(&g_SUM[t],   (double)ssum[t]);
        atomicAdd(&g_SUMSQ[t], (double)ssq2[t]);
    }
}

// ---------------- BN affine coeffs (reciprocal-mult, no DDIV); self-resets ----------------
__global__ void stats_kernel(const float* __restrict__ g, const float* __restrict__ beta,
                             double invCnt, int O, int resetMM) {
    int o = threadIdx.x;
    if (resetMM) {
        for (int i = o; i < BB*512; i += 512) { g_MXU[i] = 0u; g_MNU[i] = 0xFFFFFFFFu; }
    }
    if (o >= O) return;
    double m   = g_SUM[o]   * invCnt;
    double var = g_SUMSQ[o] * invCnt - m*m;
    float a = g[o] / sqrtf((float)var + 1e-5f);
    g_A[o]  = a;
    g_Cc[o] = beta[o] - (float)m * a;
    g_SUM[o] = 0.0; g_SUMSQ[o] = 0.0;
}

// ---------------- apply norm+lrelu, write concat features + per-point sq ----------------
template<int O>
__global__ void apply_kernel(int outOff) {
    constexpr int PPB = 256 / O;
    __shared__ float psq[PPB > 0 ? PPB : 1];
    int t = threadIdx.x;
    int p = t / O;
    int o = t - p*O;
    int n = blockIdx.x * PPB + p;
    size_t i = (size_t)n*O + o;

    if (t < PPB) psq[t] = 0.f;
    __syncthreads();

    float a = g_A[o], c = g_Cc[o];
    float sel = (a >= 0.f) ? g_YMAX[i] : g_YMIN[i];
    float v = fmaf(a, sel, c);
    v = (v >= 0.f) ? v : 0.2f*v;
    g_FEAT[(size_t)n*512 + outOff + o] = v;

    float s = v*v;
    #pragma unroll
    for (int sh = 16; sh; sh >>= 1) s += __shfl_down_sync(0xFFFFFFFFu, s, sh);
    if ((t & 31) == 0) atomicAdd(&psq[p], s);
    __syncthreads();
    if (o == 0) g_SQ[n] = psq[p];
}

// ---------------- final norm + global max + embedding ----------------
__global__ void emb_kernel(const float* __restrict__ wemb, float* __restrict__ out) {
    __shared__ float feat[512];
    int b = blockIdx.x, t = threadIdx.x;
    for (int o = t; o < 512; o += 256) {
        float a = g_A[o], c = g_Cc[o];
        float sel = (a >= 0.f) ? decf(g_MXU[b*512 + o]) : decf(g_MNU[b*512 + o]);
        float v = fmaf(a, sel, c);
        feat[o] = (v >= 0.f) ? v : 0.2f*v;
    }
    __syncthreads();
    const float* wr = wemb + (size_t)t * 512;
    float s = 0.f;
    for (int c = 0; c < 512; c++) s = fmaf(wr[c], feat[c], s);
    out[b*256 + t] = s;
}

// ---------------- host orchestration ----------------
static cudaStream_t g_sideStream = 0;
static cudaEvent_t  g_evFork = 0, g_evJoin = 0;
static const double INV_CNT_K = 1.0 / (double)(BB*NN*KNN);
static const double INV_CNT_N = 1.0 / (double)(BB*NN);

template<int C, int O>
static void run_edge_big(const float* feat, int off, const float* wcat,
                         const float* g, const float* beta, int resetMM, int outOff) {
    dim3 gg(36, 1, BB);
    dim3 zg(64, (2*O)/128, 1);
    if (g_sideStream) {
        cudaEventRecord(g_evFork, 0);
        cudaStreamWaitEvent(g_sideStream, g_evFork, 0);
        sgemm128<1><<<zg, 256, 0, g_sideStream>>>(feat + off, 512, wcat, C, C, 2*O);
        cudaEventRecord(g_evJoin, g_sideStream);
        gram_sym<<<gg, 256>>>(feat + off, 512, C);
        cudaStreamWaitEvent(0, g_evJoin, 0);
    } else {
        gram_sym<<<gg, 256>>>(feat + off, 512, C);
        sgemm128<1><<<zg, 256>>>(feat + off, 512, wcat, C, C, 2*O);
    }
    tg_kernel<O><<<BB*NN/8, 256>>>();
    stats_kernel<<<1, 512>>>(g, beta, INV_CNT_K, O, resetMM);
    apply_kernel<O><<<BB*NN/(256/O), 256>>>(outOff);
}

extern "C" void kernel_launch(void* const* d_in, const int* in_sizes, int n_in,
                              void* d_out, int out_size) {
    (void)in_sizes; (void)n_in; (void)out_size;
    const float* x    = (const float*)d_in[0];
    const float* w1   = (const float*)d_in[1];
    const float* g1   = (const float*)d_in[2];
    const float* b1   = (const float*)d_in[3];
    const float* w2   = (const float*)d_in[4];
    const float* g2   = (const float*)d_in[5];
    const float* b2   = (const float*)d_in[6];
    const float* w3   = (const float*)d_in[7];
    const float* g3   = (const float*)d_in[8];
    const float* b3   = (const float*)d_in[9];
    const float* w4   = (const float*)d_in[10];
    const float* g4   = (const float*)d_in[11];
    const float* b4   = (const float*)d_in[12];
    const float* w5   = (const float*)d_in[13];
    const float* g5   = (const float*)d_in[14];
    const float* b5   = (const float*)d_in[15];
    const float* wemb = (const float*)d_in[16];
    float* out = (float*)d_out;

    float *feat, *wcat;
    cudaGetSymbolAddress((void**)&feat, g_FEAT);
    cudaGetSymbolAddress((void**)&wcat, g_WCAT);

    if (!g_sideStream) {
        cudaStream_t s = 0;
        cudaEvent_t e1 = 0, e2 = 0;
        if (cudaStreamCreateWithFlags(&s, cudaStreamNonBlocking) == cudaSuccess &&
            cudaEventCreateWithFlags(&e1, cudaEventDisableTiming) == cudaSuccess &&
            cudaEventCreateWithFlags(&e2, cudaEventDisableTiming) == cudaSuccess) {
            g_sideStream = s; g_evFork = e1; g_evJoin = e2;
        }
    }

    prep_kernel<<<(90496 + 255)/256, 256>>>(w1, w2, w3, w4);

    // ---- stage 1 (C=3): zgemm, fused distances+topk+gather ----
    dim3 zg1(BB*NN/64, 2);
    zgemm_kernel<3, 128><<<zg1, 256>>>(x, 3, 0, wcat);
    tg1_kernel<<<BB*NN/8, 256>>>(x);
    stats_kernel<<<1, 512>>>(g1, b1, INV_CNT_K, 64, 0);
    apply_kernel<64><<<BB*NN/4, 256>>>(0);

    // ---- stages 2-4: gram || zgemm (fork), fused topk-gather ----
    run_edge_big<64,  64 >(feat, 0,   wcat + 384,   g2, b2, 0, 64);
    run_edge_big<64,  128>(feat, 64,  wcat + 8576,  g3, b3, 0, 128);
    run_edge_big<128, 256>(feat, 128, wcat + 24960, g4, b4, 1, 256);

    // ---- final conv 512x512 fused with stats + max/min ----
    dim3 g5g(64, 4, 1);
    sgemm128<2><<<g5g, 256>>>(feat, 512, w5, 512, 512, 0);
    stats_kernel<<<1, 512>>>(g5, b5, INV_CNT_N, 512, 0);
    emb_kernel<<<BB, 256>>>(wemb, out);
}